// round 1
// baseline (speedup 1.0000x reference)
#include <cuda_runtime.h>
#include <cuda_bf16.h>

#define MAX_B   32768
#define H       64
#define NTHREADS 64

__device__ int g_soff[MAX_B];   // exclusive prefix of size
__device__ int g_toff[MAX_B];   // exclusive prefix of target_size

// ---------------------------------------------------------------------------
// Kernel 1: exclusive scan of size[] and target_size[] (B <= MAX_B).
// Single block, 1024 threads, chunked Hillis-Steele.
// ---------------------------------------------------------------------------
__global__ void scan_offsets_kernel(const int* __restrict__ size,
                                    const int* __restrict__ tsize,
                                    int B) {
    __shared__ int shs[1024];
    __shared__ int sht[1024];
    const int t = threadIdx.x;
    const int chunk = (B + 1023) >> 10;
    const int base = t * chunk;

    int s0 = 0, t0 = 0;
    for (int i = 0; i < chunk; i++) {
        int idx = base + i;
        if (idx < B) { s0 += size[idx]; t0 += tsize[idx]; }
    }
    shs[t] = s0; sht[t] = t0;
    __syncthreads();

    // inclusive scan over 1024 partials
    for (int o = 1; o < 1024; o <<= 1) {
        int a = 0, b = 0;
        if (t >= o) { a = shs[t - o]; b = sht[t - o]; }
        __syncthreads();
        shs[t] += a; sht[t] += b;
        __syncthreads();
    }

    int es = (t > 0) ? shs[t - 1] : 0;   // exclusive prefix at chunk start
    int et = (t > 0) ? sht[t - 1] : 0;
    for (int i = 0; i < chunk; i++) {
        int idx = base + i;
        if (idx < B) {
            g_soff[idx] = es; g_toff[idx] = et;
            es += size[idx]; et += tsize[idx];
        }
    }
}

// ---------------------------------------------------------------------------
// Fused N-value reduction across a 64-thread block (2 warps).
// ---------------------------------------------------------------------------
template <int N>
__device__ __forceinline__ void block_reduce64(float (&v)[N], float* sh) {
    #pragma unroll
    for (int o = 16; o > 0; o >>= 1) {
        #pragma unroll
        for (int k = 0; k < N; k++)
            v[k] += __shfl_xor_sync(0xffffffffu, v[k], o);
    }
    const int wid = threadIdx.x >> 5;
    if ((threadIdx.x & 31) == 0) {
        #pragma unroll
        for (int k = 0; k < N; k++) sh[k * 2 + wid] = v[k];
    }
    __syncthreads();
    #pragma unroll
    for (int k = 0; k < N; k++) v[k] = sh[k * 2] + sh[k * 2 + 1];
    __syncthreads();
}

// ---------------------------------------------------------------------------
// Kernel 2: one block per group. Thread j owns hidden lane j (H=64).
//   emb  = 0.5 * user_emb(last) + 0.5 * mean(item rows in segment)
//   out[toff+t] = <center_l2(emb), center_l2(item_weight[target])>
// ---------------------------------------------------------------------------
__global__ void __launch_bounds__(NTHREADS)
simplex_kernel(const int*   __restrict__ user,
               const int*   __restrict__ item,
               const int*   __restrict__ tgt,
               const int*   __restrict__ size,
               const int*   __restrict__ tsize,
               const float* __restrict__ uw,
               const float* __restrict__ iw,
               float*       __restrict__ out) {
    const int b    = blockIdx.x;
    const int lane = threadIdx.x;                 // 0..63 -> hidden dim index
    const int soff = g_soff[b];
    const int sz   = size[b];
    const int toff = g_toff[b];
    const int tsz  = tsize[b];

    __shared__ float red[6];                      // up to 3 values x 2 warps

    // --- segment sum of item embeddings (coalesced: 2 warps x 128B per row) ---
    float acc = 0.0f;
    #pragma unroll 4
    for (int i = 0; i < sz; i++) {
        int row = __ldg(&item[soff + i]);         // broadcast load
        acc += __ldg(&iw[(size_t)row * H + lane]);
    }

    const int urow = __ldg(&user[soff + sz - 1]);
    float emb = 0.5f * __ldg(&uw[(size_t)urow * H + lane])
              + 0.5f * acc / ((float)sz + 1e-6f);

    // --- center + L2-normalize emb: one fused pass (sum, sumsq) ---
    float v2[2] = { emb, emb * emb };
    block_reduce64<2>(v2, red);
    const float mean = v2[0] * (1.0f / H);
    float ss = v2[1] - v2[0] * mean;              // sum(x^2) - S^2/H
    ss = fmaxf(ss, 0.0f);
    const float inv_n = 1.0f / fmaxf(sqrtf(ss), 1e-12f);
    const float embn = (emb - mean) * inv_n;      // centered, normalized

    // --- targets: sum(te), sum(te^2), dot(te, embn) in one fused pass ---
    // Since sum(embn) == 0, dot(te - mean_t, embn) == dot(te, embn).
    for (int t = 0; t < tsz; t++) {
        int row = __ldg(&tgt[toff + t]);
        float te = __ldg(&iw[(size_t)row * H + lane]);
        float v3[3] = { te, te * te, te * embn };
        block_reduce64<3>(v3, red);
        if (lane == 0) {
            float mt  = v3[0] * (1.0f / H);
            float sst = fmaxf(v3[1] - v3[0] * mt, 0.0f);
            out[toff + t] = v3[2] / fmaxf(sqrtf(sst), 1e-12f);
        }
    }
}

// ---------------------------------------------------------------------------
extern "C" void kernel_launch(void* const* d_in, const int* in_sizes, int n_in,
                              void* d_out, int out_size) {
    const int*   user        = (const int*)d_in[0];
    const int*   item        = (const int*)d_in[1];
    const int*   target_item = (const int*)d_in[2];
    const int*   size        = (const int*)d_in[3];
    const int*   target_size = (const int*)d_in[4];
    const float* user_weight = (const float*)d_in[5];
    const float* item_weight = (const float*)d_in[6];
    float*       out         = (float*)d_out;

    const int B = in_sizes[3];

    scan_offsets_kernel<<<1, 1024>>>(size, target_size, B);
    simplex_kernel<<<B, NTHREADS>>>(user, item, target_item, size, target_size,
                                    user_weight, item_weight, out);
}

// round 2
// speedup vs baseline: 1.0772x; 1.0772x over previous
#include <cuda_runtime.h>
#include <cuda_bf16.h>

#define MAX_B   32768
#define H       64
#define TPB     128
#define GROUPS  8          // 8 groups x 16 threads; group owns one row at a time
#define IDX_TILE 128

__device__ int g_soff[MAX_B];   // exclusive prefix of size
__device__ int g_toff[MAX_B];   // exclusive prefix of target_size

// ---------------------------------------------------------------------------
// Kernel 1: exclusive scan of size[] and target_size[] via warp shuffles.
// Single block, 1024 threads, 2 syncthreads total.
// ---------------------------------------------------------------------------
__global__ void __launch_bounds__(1024)
scan_offsets_kernel(const int* __restrict__ size,
                    const int* __restrict__ tsize, int B) {
    const int t    = threadIdx.x;
    const int lane = t & 31;
    const int wid  = t >> 5;
    const int chunk = (B + 1023) >> 10;
    const int base  = t * chunk;

    int s0 = 0, t0 = 0;
    #pragma unroll 4
    for (int i = 0; i < chunk; i++) {
        int idx = base + i;
        if (idx < B) { s0 += size[idx]; t0 += tsize[idx]; }
    }
    // warp-inclusive scan of per-thread sums
    int si = s0, ti = t0;
    #pragma unroll
    for (int o = 1; o < 32; o <<= 1) {
        int a = __shfl_up_sync(0xffffffffu, si, o);
        int b = __shfl_up_sync(0xffffffffu, ti, o);
        if (lane >= o) { si += a; ti += b; }
    }
    __shared__ int ws[32], wt[32];
    if (lane == 31) { ws[wid] = si; wt[wid] = ti; }
    __syncthreads();
    if (wid == 0) {
        int a = ws[lane], b = wt[lane];
        #pragma unroll
        for (int o = 1; o < 32; o <<= 1) {
            int x = __shfl_up_sync(0xffffffffu, a, o);
            int y = __shfl_up_sync(0xffffffffu, b, o);
            if (lane >= o) { a += x; b += y; }
        }
        ws[lane] = a; wt[lane] = b;
    }
    __syncthreads();
    int es = (wid ? ws[wid - 1] : 0) + si - s0;   // exclusive prefix at chunk start
    int et = (wid ? wt[wid - 1] : 0) + ti - t0;
    for (int i = 0; i < chunk; i++) {
        int idx = base + i;
        if (idx < B) {
            g_soff[idx] = es; g_toff[idx] = et;
            es += size[idx]; et += tsize[idx];
        }
    }
}

// fused N-value reduction across a 16-lane group (xor offsets stay in segment)
template <int N>
__device__ __forceinline__ void group_reduce16(float (&v)[N]) {
    #pragma unroll
    for (int o = 8; o > 0; o >>= 1) {
        #pragma unroll
        for (int k = 0; k < N; k++)
            v[k] += __shfl_xor_sync(0xffffffffu, v[k], o);
    }
}

// ---------------------------------------------------------------------------
// Kernel 2: one 128-thread block per group of the batch.
//   8 row-groups of 16 threads; thread q in a group owns dims [4q, 4q+4).
//   emb = 0.5*user_emb(last) + 0.5*mean(item rows); out = <cl2(emb), cl2(tgt)>
// ---------------------------------------------------------------------------
__global__ void __launch_bounds__(TPB)
simplex_kernel(const int*   __restrict__ user,
               const int*   __restrict__ item,
               const int*   __restrict__ tgt,
               const int*   __restrict__ size,
               const int*   __restrict__ tsize,
               const float* __restrict__ uw,
               const float* __restrict__ iw,
               float*       __restrict__ out) {
    const int b   = blockIdx.x;
    const int tid = threadIdx.x;
    const int g   = tid >> 4;        // row-group 0..7
    const int q   = tid & 15;        // quad: dims 4q..4q+3

    const int soff = g_soff[b];
    const int sz   = size[b];
    const int toff = g_toff[b];
    const int tsz  = tsize[b];

    __shared__ float4 sred[GROUPS][16];   // per-group partial sums (2 KB)
    __shared__ int    sidx[IDX_TILE];

    // ---- segment sum: 8 rows in flight, float4 gathers ----
    float4 acc = make_float4(0.f, 0.f, 0.f, 0.f);
    for (int base = 0; base < sz; base += IDX_TILE) {
        int n = min(IDX_TILE, sz - base);
        if (tid < n) sidx[tid] = item[soff + base + tid];
        __syncthreads();
        #pragma unroll 4
        for (int i = g; i < n; i += GROUPS) {
            const float4 v = *(const float4*)&iw[(size_t)sidx[i] * H + 4 * q];
            acc.x += v.x; acc.y += v.y; acc.z += v.z; acc.w += v.w;
        }
        __syncthreads();
    }
    sred[g][q] = acc;
    __syncthreads();

    float4 tot = make_float4(0.f, 0.f, 0.f, 0.f);
    #pragma unroll
    for (int gg = 0; gg < GROUPS; gg++) {
        float4 v = sred[gg][q];
        tot.x += v.x; tot.y += v.y; tot.z += v.z; tot.w += v.w;
    }

    // ---- emb = 0.5*user + 0.5*mean ----
    float4 emb = make_float4(0.f, 0.f, 0.f, 0.f);
    if (sz > 0) {
        const int urow = __ldg(&user[soff + sz - 1]);
        const float4 ue = *(const float4*)&uw[(size_t)urow * H + 4 * q];
        const float inv = 0.5f / ((float)sz + 1e-6f);
        emb.x = 0.5f * ue.x + tot.x * inv;
        emb.y = 0.5f * ue.y + tot.y * inv;
        emb.z = 0.5f * ue.z + tot.z * inv;
        emb.w = 0.5f * ue.w + tot.w * inv;
    }

    // ---- center + normalize emb (replicated in every 16-lane group) ----
    float v2[2];
    v2[0] = emb.x + emb.y + emb.z + emb.w;
    v2[1] = emb.x * emb.x + emb.y * emb.y + emb.z * emb.z + emb.w * emb.w;
    group_reduce16<2>(v2);
    const float mean = v2[0] * (1.0f / H);
    float ss = fmaxf(v2[1] - v2[0] * mean, 0.0f);
    const float invn = 1.0f / fmaxf(sqrtf(ss), 1e-12f);
    float4 en;
    en.x = (emb.x - mean) * invn;
    en.y = (emb.y - mean) * invn;
    en.z = (emb.z - mean) * invn;
    en.w = (emb.w - mean) * invn;

    // ---- targets: group g handles t = g, g+8, ... ; sum(en)==0 so
    //      dot(center(te), en) == dot(te, en) ----
    for (int t = g; t < tsz; t += GROUPS) {
        const int row = __ldg(&tgt[toff + t]);
        const float4 te = *(const float4*)&iw[(size_t)row * H + 4 * q];
        float v3[3];
        v3[0] = te.x + te.y + te.z + te.w;
        v3[1] = te.x * te.x + te.y * te.y + te.z * te.z + te.w * te.w;
        v3[2] = te.x * en.x + te.y * en.y + te.z * en.z + te.w * en.w;
        group_reduce16<3>(v3);
        if (q == 0) {
            float mt  = v3[0] * (1.0f / H);
            float sst = fmaxf(v3[1] - v3[0] * mt, 0.0f);
            out[toff + t] = v3[2] / fmaxf(sqrtf(sst), 1e-12f);
        }
    }
}

// ---------------------------------------------------------------------------
extern "C" void kernel_launch(void* const* d_in, const int* in_sizes, int n_in,
                              void* d_out, int out_size) {
    const int*   user        = (const int*)d_in[0];
    const int*   item        = (const int*)d_in[1];
    const int*   target_item = (const int*)d_in[2];
    const int*   size        = (const int*)d_in[3];
    const int*   target_size = (const int*)d_in[4];
    const float* user_weight = (const float*)d_in[5];
    const float* item_weight = (const float*)d_in[6];
    float*       out         = (float*)d_out;

    const int B = in_sizes[3];

    scan_offsets_kernel<<<1, 1024>>>(size, target_size, B);
    simplex_kernel<<<B, TPB>>>(user, item, target_item, size, target_size,
                               user_weight, item_weight, out);
}

// round 3
// speedup vs baseline: 1.6689x; 1.5493x over previous
#include <cuda_runtime.h>
#include <cuda_bf16.h>
#include <cstdint>

#define MAX_B     32768
#define H         64
#define TPB       128
#define GROUPS    8
#define ITEM_TILE 64
#define TGT_TILE  16

__device__ int g_soff[MAX_B];   // exclusive prefix of size
__device__ int g_toff[MAX_B];   // exclusive prefix of target_size

// ---------------------------------------------------------------------------
// PTX helpers
// ---------------------------------------------------------------------------
__device__ __forceinline__ uint32_t smem_u32(const void* p) {
    uint32_t a;
    asm("{ .reg .u64 t; cvta.to.shared.u64 t, %1; cvt.u32.u64 %0, t; }"
        : "=r"(a) : "l"(p));
    return a;
}

__device__ __forceinline__ void bulk256(uint32_t dst, const void* src, uint32_t mbar) {
    asm volatile(
        "cp.async.bulk.shared::cluster.global.mbarrier::complete_tx::bytes "
        "[%0], [%1], 256, [%2];"
        :: "r"(dst), "l"(src), "r"(mbar) : "memory");
}

__device__ __forceinline__ void mbar_init(uint32_t mbar, int count) {
    asm volatile("mbarrier.init.shared.b64 [%0], %1;" :: "r"(mbar), "r"(count) : "memory");
}
__device__ __forceinline__ void mbar_expect(uint32_t mbar, uint32_t bytes) {
    asm volatile("mbarrier.arrive.expect_tx.shared.b64 _, [%0], %1;"
                 :: "r"(mbar), "r"(bytes) : "memory");
}
__device__ __forceinline__ void mbar_wait(uint32_t mbar, int phase) {
    asm volatile(
        "{\n\t.reg .pred P;\n\t"
        "W%=:\n\t"
        "mbarrier.try_wait.parity.acquire.cta.shared::cta.b64 P, [%0], %1, 0x989680;\n\t"
        "@!P bra W%=;\n\t"
        "}" :: "r"(mbar), "r"(phase) : "memory");
}

template <int N>
__device__ __forceinline__ void group_reduce16(float (&v)[N]) {
    #pragma unroll
    for (int o = 8; o > 0; o >>= 1) {
        #pragma unroll
        for (int k = 0; k < N; k++)
            v[k] += __shfl_xor_sync(0xffffffffu, v[k], o);
    }
}

// ---------------------------------------------------------------------------
// Kernel 1: exclusive scan of size[] and target_size[].
// 1 block x 1024 threads, coalesced int4 tiles of 4096 elements.
// ---------------------------------------------------------------------------
__global__ void __launch_bounds__(1024)
scan_kernel(const int* __restrict__ size, const int* __restrict__ tsize, int B) {
    __shared__ int sw[32], tw[32];
    const int t = threadIdx.x, lane = t & 31, wid = t >> 5;
    int carry_s = 0, carry_t = 0;

    for (int base = 0; base < B; base += 4096) {
        const int e0 = base + t * 4;
        int4 sv = make_int4(0, 0, 0, 0), tv = make_int4(0, 0, 0, 0);
        if (e0 + 3 < B) {
            sv = *(const int4*)(size + e0);
            tv = *(const int4*)(tsize + e0);
        } else if (e0 < B) {
            const int n = B - e0;
            if (n > 0) { sv.x = size[e0];     tv.x = tsize[e0]; }
            if (n > 1) { sv.y = size[e0 + 1]; tv.y = tsize[e0 + 1]; }
            if (n > 2) { sv.z = size[e0 + 2]; tv.z = tsize[e0 + 2]; }
        }
        const int s_tot = sv.x + sv.y + sv.z + sv.w;
        const int t_tot = tv.x + tv.y + tv.z + tv.w;

        int si = s_tot, ti = t_tot;          // warp inclusive scan
        #pragma unroll
        for (int o = 1; o < 32; o <<= 1) {
            int a = __shfl_up_sync(0xffffffffu, si, o);
            int b = __shfl_up_sync(0xffffffffu, ti, o);
            if (lane >= o) { si += a; ti += b; }
        }
        if (lane == 31) { sw[wid] = si; tw[wid] = ti; }
        __syncthreads();
        if (wid == 0) {
            int a = sw[lane], b = tw[lane];
            #pragma unroll
            for (int o = 1; o < 32; o <<= 1) {
                int x = __shfl_up_sync(0xffffffffu, a, o);
                int y = __shfl_up_sync(0xffffffffu, b, o);
                if (lane >= o) { a += x; b += y; }
            }
            sw[lane] = a; tw[lane] = b;
        }
        __syncthreads();

        int se = carry_s + (wid ? sw[wid - 1] : 0) + si - s_tot;
        int te = carry_t + (wid ? tw[wid - 1] : 0) + ti - t_tot;
        if (e0 + 3 < B) {
            *(int4*)(g_soff + e0) = make_int4(se, se + sv.x, se + sv.x + sv.y,
                                              se + sv.x + sv.y + sv.z);
            *(int4*)(g_toff + e0) = make_int4(te, te + tv.x, te + tv.x + tv.y,
                                              te + tv.x + tv.y + tv.z);
        } else if (e0 < B) {
            const int n = B - e0;
            if (n > 0) { g_soff[e0] = se;                 g_toff[e0] = te; }
            if (n > 1) { g_soff[e0 + 1] = se + sv.x;      g_toff[e0 + 1] = te + tv.x; }
            if (n > 2) { g_soff[e0 + 2] = se + sv.x + sv.y; g_toff[e0 + 2] = te + tv.x + tv.y; }
        }
        carry_s += sw[31]; carry_t += tw[31];
        __syncthreads();
    }
}

// ---------------------------------------------------------------------------
// Kernel 2: one 128-thread block per batch group. All embedding rows are
// gathered into SMEM with bulk-async copies (one mbarrier round), then the
// reductions run entirely out of SMEM.
// ---------------------------------------------------------------------------
__global__ void __launch_bounds__(TPB)
simplex_kernel(const int*   __restrict__ user,
               const int*   __restrict__ item,
               const int*   __restrict__ tgt,
               const int*   __restrict__ size,
               const int*   __restrict__ tsize,
               const float* __restrict__ uw,
               const float* __restrict__ iw,
               float*       __restrict__ out) {
    __shared__ __align__(16) float s_item[ITEM_TILE * H];   // 16 KB
    __shared__ __align__(16) float s_tgt[TGT_TILE * H];     //  4 KB
    __shared__ __align__(16) float s_user[H];               // 256 B
    __shared__ __align__(16) float4 sred[GROUPS][16];       //  2 KB
    __shared__ __align__(8)  unsigned long long mbar_storage;

    const int b   = blockIdx.x;
    const int tid = threadIdx.x;
    const int g   = tid >> 4;        // row-group 0..7
    const int q   = tid & 15;        // quad: dims 4q..4q+3

    const int soff = g_soff[b];
    const int toff = g_toff[b];
    const int sz   = size[b];
    const int tsz  = tsize[b];

    const uint32_t mbar  = smem_u32(&mbar_storage);
    const uint32_t it_sm = smem_u32(s_item);
    const uint32_t tg_sm = smem_u32(s_tgt);
    const uint32_t us_sm = smem_u32(s_user);

    if (tid == 0) mbar_init(mbar, 1);
    __syncthreads();
    int ph = 0;

    // ---- round 0: user row + first item tile + first target tile ----
    const int n_i0 = min(sz, ITEM_TILE);
    const int n_t0 = min(tsz, TGT_TILE);
    if (tid == 0) mbar_expect(mbar, (uint32_t)(n_i0 + n_t0 + 1) * 256u);
    __syncthreads();
    if (tid < n_i0) {
        const int row = __ldg(&item[soff + tid]);
        bulk256(it_sm + (uint32_t)tid * 256u, iw + (size_t)row * H, mbar);
    } else if (tid < n_i0 + n_t0) {
        const int j = tid - n_i0;
        const int row = __ldg(&tgt[toff + j]);
        bulk256(tg_sm + (uint32_t)j * 256u, iw + (size_t)row * H, mbar);
    } else if (tid == TPB - 1) {
        const int ui = max(soff + sz - 1, 0);
        const int urow = __ldg(&user[ui]);
        bulk256(us_sm, uw + (size_t)urow * H, mbar);
    }
    mbar_wait(mbar, ph); ph ^= 1;

    // ---- accumulate item rows from SMEM ----
    float4 acc = make_float4(0.f, 0.f, 0.f, 0.f);
    #pragma unroll 4
    for (int i = g; i < n_i0; i += GROUPS) {
        const float4 v = *(const float4*)&s_item[i * H + 4 * q];
        acc.x += v.x; acc.y += v.y; acc.z += v.z; acc.w += v.w;
    }
    // further item tiles (not hit when sz <= 64)
    for (int base = ITEM_TILE; base < sz; base += ITEM_TILE) {
        __syncthreads();
        const int n = min(sz - base, ITEM_TILE);
        if (tid == 0) mbar_expect(mbar, (uint32_t)n * 256u);
        __syncthreads();
        if (tid < n) {
            const int row = __ldg(&item[soff + base + tid]);
            bulk256(it_sm + (uint32_t)tid * 256u, iw + (size_t)row * H, mbar);
        }
        mbar_wait(mbar, ph); ph ^= 1;
        for (int i = g; i < n; i += GROUPS) {
            const float4 v = *(const float4*)&s_item[i * H + 4 * q];
            acc.x += v.x; acc.y += v.y; acc.z += v.z; acc.w += v.w;
        }
    }

    // ---- combine the 8 group partials ----
    sred[g][q] = acc;
    __syncthreads();
    float4 tot = make_float4(0.f, 0.f, 0.f, 0.f);
    #pragma unroll
    for (int gg = 0; gg < GROUPS; gg++) {
        const float4 v = sred[gg][q];
        tot.x += v.x; tot.y += v.y; tot.z += v.z; tot.w += v.w;
    }

    // ---- emb = 0.5*user + 0.5*mean ----
    const float4 ue = *(const float4*)&s_user[4 * q];
    const float inv = 0.5f / ((float)sz + 1e-6f);
    float4 emb;
    emb.x = 0.5f * ue.x + tot.x * inv;
    emb.y = 0.5f * ue.y + tot.y * inv;
    emb.z = 0.5f * ue.z + tot.z * inv;
    emb.w = 0.5f * ue.w + tot.w * inv;

    // ---- center + normalize emb (within each 16-lane group) ----
    float v2[2];
    v2[0] = emb.x + emb.y + emb.z + emb.w;
    v2[1] = emb.x * emb.x + emb.y * emb.y + emb.z * emb.z + emb.w * emb.w;
    group_reduce16<2>(v2);
    const float mean = v2[0] * (1.0f / H);
    const float ss   = fmaxf(v2[1] - v2[0] * mean, 0.0f);
    const float invn = 1.0f / fmaxf(sqrtf(ss), 1e-12f);
    float4 en;
    en.x = (emb.x - mean) * invn;
    en.y = (emb.y - mean) * invn;
    en.z = (emb.z - mean) * invn;
    en.w = (emb.w - mean) * invn;

    // ---- targets from SMEM: sum(en)==0 so dot(center(te), en)==dot(te, en) ----
    for (int t = g; t < n_t0; t += GROUPS) {
        const float4 te = *(const float4*)&s_tgt[t * H + 4 * q];
        float v3[3];
        v3[0] = te.x + te.y + te.z + te.w;
        v3[1] = te.x * te.x + te.y * te.y + te.z * te.z + te.w * te.w;
        v3[2] = te.x * en.x + te.y * en.y + te.z * en.z + te.w * en.w;
        group_reduce16<3>(v3);
        if (q == 0) {
            const float mt  = v3[0] * (1.0f / H);
            const float sst = fmaxf(v3[1] - v3[0] * mt, 0.0f);
            out[toff + t] = v3[2] / fmaxf(sqrtf(sst), 1e-12f);
        }
    }
    // further target tiles (not hit when tsz <= 16)
    for (int base = TGT_TILE; base < tsz; base += TGT_TILE) {
        __syncthreads();
        const int n = min(tsz - base, TGT_TILE);
        if (tid == 0) mbar_expect(mbar, (uint32_t)n * 256u);
        __syncthreads();
        if (tid < n) {
            const int row = __ldg(&tgt[toff + base + tid]);
            bulk256(tg_sm + (uint32_t)tid * 256u, iw + (size_t)row * H, mbar);
        }
        mbar_wait(mbar, ph); ph ^= 1;
        for (int t = g; t < n; t += GROUPS) {
            const float4 te = *(const float4*)&s_tgt[t * H + 4 * q];
            float v3[3];
            v3[0] = te.x + te.y + te.z + te.w;
            v3[1] = te.x * te.x + te.y * te.y + te.z * te.z + te.w * te.w;
            v3[2] = te.x * en.x + te.y * en.y + te.z * en.z + te.w * en.w;
            group_reduce16<3>(v3);
            if (q == 0) {
                const float mt  = v3[0] * (1.0f / H);
                const float sst = fmaxf(v3[1] - v3[0] * mt, 0.0f);
                out[toff + base + t] = v3[2] / fmaxf(sqrtf(sst), 1e-12f);
            }
        }
    }
}

// ---------------------------------------------------------------------------
extern "C" void kernel_launch(void* const* d_in, const int* in_sizes, int n_in,
                              void* d_out, int out_size) {
    const int*   user        = (const int*)d_in[0];
    const int*   item        = (const int*)d_in[1];
    const int*   target_item = (const int*)d_in[2];
    const int*   size        = (const int*)d_in[3];
    const int*   target_size = (const int*)d_in[4];
    const float* user_weight = (const float*)d_in[5];
    const float* item_weight = (const float*)d_in[6];
    float*       out         = (float*)d_out;

    const int B = in_sizes[3];

    scan_kernel<<<1, 1024>>>(size, target_size, B);
    simplex_kernel<<<B, TPB>>>(user, item, target_item, size, target_size,
                               user_weight, item_weight, out);
}

// round 4
// speedup vs baseline: 2.3677x; 1.4187x over previous
#include <cuda_runtime.h>
#include <cuda_bf16.h>
#include <cstdint>

#define MAX_B  32768
#define H      64
#define TPB    256          // 8 warps = 8 batch groups per block

__device__ int g_soff[MAX_B];   // exclusive prefix of size
__device__ int g_toff[MAX_B];   // exclusive prefix of target_size

// ---------------------------------------------------------------------------
// Kernel 1: exclusive scan of size[] and target_size[].
// ---------------------------------------------------------------------------
__global__ void __launch_bounds__(1024)
scan_kernel(const int* __restrict__ size, const int* __restrict__ tsize, int B) {
    __shared__ int sw[32], tw[32];
    const int t = threadIdx.x, lane = t & 31, wid = t >> 5;
    int carry_s = 0, carry_t = 0;

    for (int base = 0; base < B; base += 4096) {
        const int e0 = base + t * 4;
        int4 sv = make_int4(0, 0, 0, 0), tv = make_int4(0, 0, 0, 0);
        if (e0 + 3 < B) {
            sv = *(const int4*)(size + e0);
            tv = *(const int4*)(tsize + e0);
        } else if (e0 < B) {
            const int n = B - e0;
            if (n > 0) { sv.x = size[e0];     tv.x = tsize[e0]; }
            if (n > 1) { sv.y = size[e0 + 1]; tv.y = tsize[e0 + 1]; }
            if (n > 2) { sv.z = size[e0 + 2]; tv.z = tsize[e0 + 2]; }
        }
        const int s_tot = sv.x + sv.y + sv.z + sv.w;
        const int t_tot = tv.x + tv.y + tv.z + tv.w;

        int si = s_tot, ti = t_tot;
        #pragma unroll
        for (int o = 1; o < 32; o <<= 1) {
            int a = __shfl_up_sync(0xffffffffu, si, o);
            int b = __shfl_up_sync(0xffffffffu, ti, o);
            if (lane >= o) { si += a; ti += b; }
        }
        if (lane == 31) { sw[wid] = si; tw[wid] = ti; }
        __syncthreads();
        if (wid == 0) {
            int a = sw[lane], b = tw[lane];
            #pragma unroll
            for (int o = 1; o < 32; o <<= 1) {
                int x = __shfl_up_sync(0xffffffffu, a, o);
                int y = __shfl_up_sync(0xffffffffu, b, o);
                if (lane >= o) { a += x; b += y; }
            }
            sw[lane] = a; tw[lane] = b;
        }
        __syncthreads();

        int se = carry_s + (wid ? sw[wid - 1] : 0) + si - s_tot;
        int te = carry_t + (wid ? tw[wid - 1] : 0) + ti - t_tot;
        if (e0 + 3 < B) {
            *(int4*)(g_soff + e0) = make_int4(se, se + sv.x, se + sv.x + sv.y,
                                              se + sv.x + sv.y + sv.z);
            *(int4*)(g_toff + e0) = make_int4(te, te + tv.x, te + tv.x + tv.y,
                                              te + tv.x + tv.y + tv.z);
        } else if (e0 < B) {
            const int n = B - e0;
            if (n > 0) { g_soff[e0] = se;                   g_toff[e0] = te; }
            if (n > 1) { g_soff[e0 + 1] = se + sv.x;        g_toff[e0 + 1] = te + tv.x; }
            if (n > 2) { g_soff[e0 + 2] = se + sv.x + sv.y; g_toff[e0 + 2] = te + tv.x + tv.y; }
        }
        carry_s += sw[31]; carry_t += tw[31];
        __syncthreads();
    }
}

// width-16 fused reduction (xor offsets stay within each half-warp)
template <int N>
__device__ __forceinline__ void red16(float (&v)[N]) {
    #pragma unroll
    for (int o = 8; o > 0; o >>= 1) {
        #pragma unroll
        for (int k = 0; k < N; k++)
            v[k] += __shfl_xor_sync(0xffffffffu, v[k], o);
    }
}

__device__ __forceinline__ float4 f4add(float4 a, float4 b) {
    return make_float4(a.x + b.x, a.y + b.y, a.z + b.z, a.w + b.w);
}

// ---------------------------------------------------------------------------
// Kernel 2: ONE WARP per batch group. 16 lanes per row (lane q owns dims
// [4q,4q+4)), two rows in flight (one per half-warp), unrolled x4 for MLP.
// No block barriers in the hot path.
// ---------------------------------------------------------------------------
__global__ void __launch_bounds__(TPB)
simplex_kernel(const int*   __restrict__ user,
               const int*   __restrict__ item,
               const int*   __restrict__ tgt,
               const int*   __restrict__ size,
               const int*   __restrict__ tsize,
               const float* __restrict__ uw,
               const float* __restrict__ iw,
               float*       __restrict__ out,
               int B) {
    const int b = blockIdx.x * (TPB >> 5) + (threadIdx.x >> 5);
    if (b >= B) return;
    const int lane = threadIdx.x & 31;
    const int q    = lane & 15;      // dim quad
    const int h    = lane >> 4;      // half-warp: which row of a pair

    const int soff = g_soff[b];
    const int toff = g_toff[b];
    const int sz   = size[b];
    const int tsz  = tsize[b];

    // ---- segment sum over item rows ----
    float4 acc = make_float4(0.f, 0.f, 0.f, 0.f);
    for (int cb = 0; cb < sz; cb += 64) {
        const int n = min(sz - cb, 64);
        // stash up to 64 indices in two registers (coalesced load)
        const int ia = (lane      < n) ? __ldg(&item[soff + cb + lane])      : 0;
        const int ib = (lane + 32 < n) ? __ldg(&item[soff + cb + 32 + lane]) : 0;

        int base = 0;
        for (; base + 8 <= n; base += 8) {
            const int r0 = base + 0 + h, r1 = base + 2 + h;
            const int r2 = base + 4 + h, r3 = base + 6 + h;
            const int i0 = (r0 < 32) ? __shfl_sync(0xffffffffu, ia, r0)
                                     : __shfl_sync(0xffffffffu, ib, r0 - 32);
            const int i1 = (r1 < 32) ? __shfl_sync(0xffffffffu, ia, r1)
                                     : __shfl_sync(0xffffffffu, ib, r1 - 32);
            const int i2 = (r2 < 32) ? __shfl_sync(0xffffffffu, ia, r2)
                                     : __shfl_sync(0xffffffffu, ib, r2 - 32);
            const int i3 = (r3 < 32) ? __shfl_sync(0xffffffffu, ia, r3)
                                     : __shfl_sync(0xffffffffu, ib, r3 - 32);
            // 4 independent gathers in flight per lane
            const float4 v0 = __ldg((const float4*)&iw[(size_t)i0 * H + 4 * q]);
            const float4 v1 = __ldg((const float4*)&iw[(size_t)i1 * H + 4 * q]);
            const float4 v2 = __ldg((const float4*)&iw[(size_t)i2 * H + 4 * q]);
            const float4 v3 = __ldg((const float4*)&iw[(size_t)i3 * H + 4 * q]);
            acc = f4add(acc, f4add(f4add(v0, v1), f4add(v2, v3)));
        }
        for (; base < n; base += 2) {
            const int r = base + h;
            if (r < n) {
                const int ii = (r < 32) ? __shfl_sync(0xffffffffu, ia, r)
                                        : __shfl_sync(0xffffffffu, ib, r - 32);
                acc = f4add(acc, __ldg((const float4*)&iw[(size_t)ii * H + 4 * q]));
            }
        }
    }
    // combine the two half-warp row streams (both halves hold the same quad q)
    acc.x += __shfl_xor_sync(0xffffffffu, acc.x, 16);
    acc.y += __shfl_xor_sync(0xffffffffu, acc.y, 16);
    acc.z += __shfl_xor_sync(0xffffffffu, acc.z, 16);
    acc.w += __shfl_xor_sync(0xffffffffu, acc.w, 16);

    // ---- emb = 0.5*user + 0.5*mean ----
    const int ui   = max(soff + sz - 1, 0);
    const int urow = __ldg(&user[ui]);
    const float4 ue = __ldg((const float4*)&uw[(size_t)urow * H + 4 * q]);
    const float inv = 0.5f / ((float)sz + 1e-6f);
    float4 emb;
    emb.x = 0.5f * ue.x + acc.x * inv;
    emb.y = 0.5f * ue.y + acc.y * inv;
    emb.z = 0.5f * ue.z + acc.z * inv;
    emb.w = 0.5f * ue.w + acc.w * inv;

    // ---- center + L2 normalize (width-16, replicated in both halves) ----
    float v2r[2];
    v2r[0] = emb.x + emb.y + emb.z + emb.w;
    v2r[1] = emb.x * emb.x + emb.y * emb.y + emb.z * emb.z + emb.w * emb.w;
    red16<2>(v2r);
    const float mean = v2r[0] * (1.0f / H);
    const float ss   = fmaxf(v2r[1] - v2r[0] * mean, 0.0f);
    const float invn = 1.0f / fmaxf(sqrtf(ss), 1e-12f);
    float4 en;
    en.x = (emb.x - mean) * invn;
    en.y = (emb.y - mean) * invn;
    en.z = (emb.z - mean) * invn;
    en.w = (emb.w - mean) * invn;

    // ---- targets: two per iteration (one per half). sum(en)==0 so
    //      dot(center(te), en) == dot(te, en). ----
    for (int cb = 0; cb < tsz; cb += 32) {
        const int n  = min(tsz - cb, 32);
        const int ta = (lane < n) ? __ldg(&tgt[toff + cb + lane]) : 0;
        for (int base = 0; base < n; base += 2) {
            const int t = base + h;
            if (t < n) {
                const int row = __shfl_sync(0xffffffffu, ta, t);
                const float4 te = __ldg((const float4*)&iw[(size_t)row * H + 4 * q]);
                float v3[3];
                v3[0] = te.x + te.y + te.z + te.w;
                v3[1] = te.x * te.x + te.y * te.y + te.z * te.z + te.w * te.w;
                v3[2] = te.x * en.x + te.y * en.y + te.z * en.z + te.w * en.w;
                red16<3>(v3);
                if (q == 0) {
                    const float mt  = v3[0] * (1.0f / H);
                    const float sst = fmaxf(v3[1] - v3[0] * mt, 0.0f);
                    out[toff + cb + t] = v3[2] / fmaxf(sqrtf(sst), 1e-12f);
                }
            }
        }
    }
}

// ---------------------------------------------------------------------------
extern "C" void kernel_launch(void* const* d_in, const int* in_sizes, int n_in,
                              void* d_out, int out_size) {
    const int*   user        = (const int*)d_in[0];
    const int*   item        = (const int*)d_in[1];
    const int*   target_item = (const int*)d_in[2];
    const int*   size        = (const int*)d_in[3];
    const int*   target_size = (const int*)d_in[4];
    const float* user_weight = (const float*)d_in[5];
    const float* item_weight = (const float*)d_in[6];
    float*       out         = (float*)d_out;

    const int B = in_sizes[3];
    const int warps_per_block = TPB >> 5;
    const int grid = (B + warps_per_block - 1) / warps_per_block;

    scan_kernel<<<1, 1024>>>(size, target_size, B);
    simplex_kernel<<<grid, TPB>>>(user, item, target_item, size, target_size,
                                  user_weight, item_weight, out, B);
}